// round 14
// baseline (speedup 1.0000x reference)
#include <cuda_runtime.h>
#include <cuda_bf16.h>
#include <stdint.h>

#define BATCH 4
#define SEQ   2048
#define DIM   1024
#define HEADS 16
#define TDIM  3072

#if !defined(__CUDA_ARCH__)
#define TC_OK 0
#elif defined(__CUDA_ARCH_FEAT_SM103_ALL) || defined(__CUDA_ARCH_FEAT_SM100_ALL) || \
      defined(__CUDA_ARCH_SPECIFIC__) || defined(__CUDA_ARCH_FAMILY_SPECIFIC__)
#define TC_OK 1
#else
#define TC_OK 0
#endif

// ---------------- scratch ----------------
__device__ __align__(256) float g_qkv[BATCH * SEQ * TDIM];
__device__ __align__(256) float g_E[(size_t)BATCH * HEADS * SEQ * SEQ];  // exp(s/8), 1.07GB
__device__ __align__(256) float g_Z[(size_t)BATCH * SEQ * SEQ];          // sum over heads -> 1/Z
__device__ __align__(256) __nv_bfloat16 g_xh[BATCH * SEQ * DIM];
__device__ __align__(256) __nv_bfloat16 g_xl[BATCH * SEQ * DIM];
__device__ __align__(256) __nv_bfloat16 g_wqh[TDIM * DIM];
__device__ __align__(256) __nv_bfloat16 g_wql[TDIM * DIM];
__device__ __align__(256) __nv_bfloat16 g_woh[DIM * DIM];
__device__ __align__(256) __nv_bfloat16 g_wol[DIM * DIM];
__device__ __align__(256) __nv_bfloat16 g_qhh[BATCH * HEADS * SEQ * 64];
__device__ __align__(256) __nv_bfloat16 g_qhl[BATCH * HEADS * SEQ * 64];
__device__ __align__(256) __nv_bfloat16 g_khh[BATCH * HEADS * SEQ * 64];
__device__ __align__(256) __nv_bfloat16 g_khl[BATCH * HEADS * SEQ * 64];
__device__ __align__(256) __nv_bfloat16 g_vth[BATCH * HEADS * 64 * SEQ];
__device__ __align__(256) __nv_bfloat16 g_vtl[BATCH * HEADS * 64 * SEQ];
__device__ __align__(256) __nv_bfloat16 g_ath[BATCH * SEQ * DIM];
__device__ __align__(256) __nv_bfloat16 g_atl[BATCH * SEQ * DIM];

// ---------------- PTX helpers ----------------
__device__ __forceinline__ uint32_t smem_u32(const void* p) {
    return (uint32_t)__cvta_generic_to_shared(p);
}
__device__ __forceinline__ uint32_t elect_one() {
    uint32_t pred;
    asm volatile("{\n\t.reg .pred p;\n\telect.sync _|p, 0xFFFFFFFF;\n\tselp.b32 %0, 1, 0, p;\n\t}"
                 : "=r"(pred));
    return pred;
}
#define MBAR_INIT(a, c) \
    asm volatile("mbarrier.init.shared.b64 [%0], %1;" :: "r"(a), "r"(c) : "memory")
#define MBAR_WAIT(addr, par) do {                                               \
    uint32_t _m = (addr), _p = (par), _d;                                       \
    asm volatile("{\n\t.reg .pred p;\n\t"                                       \
        "mbarrier.try_wait.parity.acquire.cta.shared::cta.b64 p, [%1], %2;\n\t" \
        "selp.b32 %0, 1, 0, p;\n\t}" : "=r"(_d) : "r"(_m), "r"(_p) : "memory"); \
    if (!_d) {                                                                  \
        asm volatile("{\n\t.reg .pred P1;\n\t"                                  \
        "WL_%=:\n\t"                                                            \
        "mbarrier.try_wait.parity.acquire.cta.shared::cta.b64 P1, [%0], %1, 0x989680;\n\t" \
        "@P1 bra.uni WD_%=;\n\tbra.uni WL_%=;\n\tWD_%=:\n\t}"                   \
        :: "r"(_m), "r"(_p) : "memory");                                        \
    }                                                                           \
} while (0)
#define TC_ALLOC(sa, n) \
    asm volatile("tcgen05.alloc.cta_group::1.sync.aligned.shared::cta.b32 [%0], %1;" :: "r"(sa), "r"(n) : "memory")
#define TC_DEALLOC(t, n) \
    asm volatile("tcgen05.dealloc.cta_group::1.sync.aligned.b32 %0, %1;" :: "r"(t), "r"(n))
#define TC_RELINQ() \
    asm volatile("tcgen05.relinquish_alloc_permit.cta_group::1.sync.aligned;")
#define TC_COMMIT(a) \
    asm volatile("tcgen05.commit.cta_group::1.mbarrier::arrive::one.shared::cluster.b64 [%0];" :: "r"(a) : "memory")
#define TC_FENCE_AFTER()  asm volatile("tcgen05.fence::after_thread_sync;" ::: "memory")
#define TC_WAIT_LD()      asm volatile("tcgen05.wait::ld.sync.aligned;" ::: "memory")
#define FENCE_ASYNC()     asm volatile("fence.proxy.async.shared::cta;" ::: "memory")

#define CP_ASYNC16(dst, src) \
    asm volatile("cp.async.cg.shared.global [%0], [%1], 16;" :: "r"(dst), "l"(src) : "memory")
#define CP_COMMIT() asm volatile("cp.async.commit_group;" ::: "memory")
#define CP_WAIT(n)  asm volatile("cp.async.wait_group %0;" :: "n"(n) : "memory")

#define TC_LD_X32(r, a) \
    asm volatile( \
        "tcgen05.ld.sync.aligned.32x32b.x32.b32 " \
        "{%0, %1, %2, %3, %4, %5, %6, %7, %8, %9, %10, %11, %12, %13, %14, %15, " \
        " %16, %17, %18, %19, %20, %21, %22, %23, %24, %25, %26, %27, %28, %29, %30, %31}, [%32];" \
        : "=r"((r)[0]),  "=r"((r)[1]),  "=r"((r)[2]),  "=r"((r)[3]), \
          "=r"((r)[4]),  "=r"((r)[5]),  "=r"((r)[6]),  "=r"((r)[7]), \
          "=r"((r)[8]),  "=r"((r)[9]),  "=r"((r)[10]), "=r"((r)[11]), \
          "=r"((r)[12]), "=r"((r)[13]), "=r"((r)[14]), "=r"((r)[15]), \
          "=r"((r)[16]), "=r"((r)[17]), "=r"((r)[18]), "=r"((r)[19]), \
          "=r"((r)[20]), "=r"((r)[21]), "=r"((r)[22]), "=r"((r)[23]), \
          "=r"((r)[24]), "=r"((r)[25]), "=r"((r)[26]), "=r"((r)[27]), \
          "=r"((r)[28]), "=r"((r)[29]), "=r"((r)[30]), "=r"((r)[31]) \
        : "r"(a))

#define SWZ(x) ((x) ^ (((x) >> 3) & 0x70))

__device__ __forceinline__ uint64_t make_desc(uint32_t addr) {
    const uint64_t base =
        (uint64_t(2) << 61) | (uint64_t(1) << 46) | (uint64_t(64) << 32) | (uint64_t(1) << 16);
    return base | ((addr >> 4) & 0x3FFF);
}
#if defined(__CUDA_ARCH__) && TC_OK
__device__ __forceinline__ void mma_bf16(uint32_t d, uint64_t ad, uint64_t bd,
                                         uint32_t idesc, uint32_t en) {
    asm volatile(
        "{\n\t.reg .pred p;\n\tsetp.ne.u32 p, %5, 0;\n\t"
        "tcgen05.mma.cta_group::1.kind::f16 [%0], %1, %2, %3, {%4, %4, %4, %4}, p;\n\t}"
        :: "r"(d), "l"(ad), "l"(bd), "r"(idesc), "r"(0u), "r"(en) : "memory");
}
#endif

__device__ __forceinline__ void split4(float4 p, uint2& hv, uint2& lv) {
    __nv_bfloat16 h0 = __float2bfloat16(p.x), h1 = __float2bfloat16(p.y);
    __nv_bfloat16 h2 = __float2bfloat16(p.z), h3 = __float2bfloat16(p.w);
    __nv_bfloat16 l0 = __float2bfloat16(p.x - __bfloat162float(h0));
    __nv_bfloat16 l1 = __float2bfloat16(p.y - __bfloat162float(h1));
    __nv_bfloat16 l2 = __float2bfloat16(p.z - __bfloat162float(h2));
    __nv_bfloat16 l3 = __float2bfloat16(p.w - __bfloat162float(h3));
    __nv_bfloat162 a, b, c, d;
    a.x = h0; a.y = h1; b.x = h2; b.y = h3;
    c.x = l0; c.y = l1; d.x = l2; d.y = l3;
    hv.x = *(uint32_t*)&a; hv.y = *(uint32_t*)&b;
    lv.x = *(uint32_t*)&c; lv.y = *(uint32_t*)&d;
}

// ---------------- conversion kernels ----------------
__global__ void __launch_bounds__(256) split_kernel(const float4* __restrict__ src,
                                                    __nv_bfloat16* __restrict__ hi,
                                                    __nv_bfloat16* __restrict__ lo, int n4) {
    int i = blockIdx.x * 256 + threadIdx.x;
    if (i >= n4) return;
    uint2 hv, lv;
    split4(src[i], hv, lv);
    *(uint2*)(hi + (size_t)i * 4) = hv;
    *(uint2*)(lo + (size_t)i * 4) = lv;
}

__global__ void __launch_bounds__(256) transpose_split_kernel(
    const float* __restrict__ W, __nv_bfloat16* __restrict__ Th,
    __nv_bfloat16* __restrict__ Tl, int K, int N) {
    __shared__ float t[32][33];
    const int n0 = blockIdx.x * 32, k0 = blockIdx.y * 32;
    const int tx = threadIdx.x, ty = threadIdx.y;
    #pragma unroll
    for (int j = 0; j < 32; j += 8)
        t[ty + j][tx] = W[(size_t)(k0 + ty + j) * N + n0 + tx];
    __syncthreads();
    #pragma unroll
    for (int j = 0; j < 32; j += 8) {
        float v = t[tx][ty + j];
        size_t o = (size_t)(n0 + ty + j) * K + k0 + tx;
        __nv_bfloat16 h = __float2bfloat16(v);
        Th[o] = h;
        Tl[o] = __float2bfloat16(v - __bfloat162float(h));
    }
}

__global__ void __launch_bounds__(256) conv_qk_kernel() {
    int i4 = blockIdx.x * 256 + threadIdx.x;
    int k4 = i4 & 15;
    int l  = (i4 >> 4) & 2047;
    int h  = (i4 >> 15) & 15;
    int b  = i4 >> 19;
    const float* row = g_qkv + (size_t)b * SEQ * TDIM
                     + (size_t)(h * 128 + (l >> 4)) * TDIM + (l & 15) * 64 + k4 * 4;
    size_t o = (size_t)i4 * 4;
    uint2 hv, lv;
    split4(*(const float4*)row, hv, lv);
    *(uint2*)(g_qhh + o) = hv; *(uint2*)(g_qhl + o) = lv;
    split4(*(const float4*)(row + 1024), hv, lv);
    *(uint2*)(g_khh + o) = hv; *(uint2*)(g_khl + o) = lv;
}

__global__ void __launch_bounds__(256) conv_vt_kernel() {
    __shared__ float t[64][65];
    const int z = blockIdx.y;
    const int b = z >> 4, h = z & 15;
    const int m0 = blockIdx.x * 64;
    const int tid = threadIdx.x;
    for (int idx = tid; idx < 1024; idx += 256) {
        int r = idx >> 4, c4 = idx & 15;
        int m = m0 + r;
        const float* row = g_qkv + (size_t)b * SEQ * TDIM
                         + (size_t)(h * 128 + (m >> 4)) * TDIM + (m & 15) * 64 + 2048 + c4 * 4;
        float4 v = *(const float4*)row;
        t[r][c4 * 4 + 0] = v.x; t[r][c4 * 4 + 1] = v.y;
        t[r][c4 * 4 + 2] = v.z; t[r][c4 * 4 + 3] = v.w;
    }
    __syncthreads();
    for (int idx = tid; idx < 1024; idx += 256) {
        int kk = idx >> 4, c4 = idx & 15;
        float4 v;
        v.x = t[c4 * 4 + 0][kk]; v.y = t[c4 * 4 + 1][kk];
        v.z = t[c4 * 4 + 2][kk]; v.w = t[c4 * 4 + 3][kk];
        size_t o = ((size_t)z * 64 + kk) * SEQ + m0 + c4 * 4;
        uint2 hv, lv;
        split4(v, hv, lv);
        *(uint2*)(g_vth + o) = hv;
        *(uint2*)(g_vtl + o) = lv;
    }
}

// reciprocal in place: Z -> 1/Z
__global__ void __launch_bounds__(256) rcp_kernel(float4* __restrict__ Z, int n4) {
    int i = blockIdx.x * 256 + threadIdx.x;
    if (i >= n4) return;
    float4 z = Z[i];
    z.x = 1.0f / z.x; z.y = 1.0f / z.y; z.z = 1.0f / z.z; z.w = 1.0f / z.w;
    Z[i] = z;
}

// ---------------- tcgen05 bf16x3 GEMM, MMA-first 3-stage pipeline ----------------
// EPI=0: C = scale * acc (fp32).  EPI=1: C = exp(scale*acc), atomicAdd g_Z.
template <int EPI>
__global__ void __launch_bounds__(256, 1) gemm_tc(
    const __nv_bfloat16* __restrict__ Ah, const __nv_bfloat16* __restrict__ Al,
    const __nv_bfloat16* __restrict__ Bh, const __nv_bfloat16* __restrict__ Bl,
    float* __restrict__ C, int K, int ldA, int ldB, int ldC,
    long long sAz, long long sBz, long long sCz, float scale)
{
    extern __shared__ char dsm[];
    uint32_t raw = smem_u32(dsm);
    uint32_t sbase = (raw + 1023) & ~1023u;
    const int tid = threadIdx.x, wid = tid >> 5, lid = tid & 31;
    const int z = blockIdx.z;
    const int row0 = blockIdx.y * 128, col0 = blockIdx.x * 128;
    Ah += (size_t)z * sAz; Al += (size_t)z * sAz;
    Bh += (size_t)z * sBz; Bl += (size_t)z * sBz;
    C  += (size_t)z * sCz;
#if TC_OK
    const int STAGE = 65536;
    uint32_t MBarr[3] = {sbase + 8, sbase + 16, sbase + 24};

    if (wid == 0) {
        if (elect_one()) { MBAR_INIT(MBarr[0], 1); MBAR_INIT(MBarr[1], 1); MBAR_INIT(MBarr[2], 1); }
        TC_ALLOC(sbase, 128);
        TC_RELINQ();
    }
    __syncthreads();
    uint32_t tmem;
    asm volatile("ld.shared.b32 %0, [%1];" : "=r"(tmem) : "r"(sbase));

    const uint32_t IDESC = (1u << 4) | (1u << 7) | (1u << 10) | (16u << 17) | (8u << 24);
    const int T = K >> 6;
    const int lr = tid >> 1;
    const int lc = (tid & 1) * 4;

    auto load_tile = [&](int t, int buf) {
        uint32_t sb = sbase + 1024 + buf * STAGE;
        const int k0 = t * 64;
        #pragma unroll
        for (int c = 0; c < 4; ++c) {
            int cc = lc + c;
            size_t ao = (size_t)(row0 + lr) * ldA + k0 + cc * 8;
            size_t bo = (size_t)(col0 + lr) * ldB + k0 + cc * 8;
            uint32_t off = SWZ(lr * 128 + cc * 16);
            CP_ASYNC16(sb + off,         Ah + ao);
            CP_ASYNC16(sb + 16384 + off, Al + ao);
            CP_ASYNC16(sb + 32768 + off, Bh + bo);
            CP_ASYNC16(sb + 49152 + off, Bl + bo);
        }
    };

    uint32_t ph[3] = {0, 0, 0};
    load_tile(0, 0); CP_COMMIT();
    if (T > 1) { load_tile(1, 1); CP_COMMIT(); }
    for (int t = 0; t < T; ++t) {
        const int s = t % 3;
        // tile t arrival (newest pending group is t+1 if it exists)
        if (t + 1 < T) { CP_WAIT(1); } else { CP_WAIT(0); }
        __syncthreads();
        // MMA first — so the stage-reuse wait below targets an MMA issued a full
        // iteration ago (hides the ~768cyc tensor latency behind the load phase)
        if (wid == 0) {
            FENCE_ASYNC();
            if (elect_one()) {
                uint32_t sb = sbase + 1024 + s * STAGE;
                uint64_t dah = make_desc(sb), dal = make_desc(sb + 16384);
                uint64_t dbh = make_desc(sb + 32768), dbl = make_desc(sb + 49152);
                #pragma unroll
                for (int ks = 0; ks < 4; ++ks) {
                    mma_bf16(tmem, dah + ks * 2, dbh + ks * 2, IDESC, (uint32_t)((t | ks) != 0));
                    mma_bf16(tmem, dah + ks * 2, dbl + ks * 2, IDESC, 1u);
                    mma_bf16(tmem, dal + ks * 2, dbh + ks * 2, IDESC, 1u);
                }
                TC_COMMIT(MBarr[s]);
            }
        }
        if (t + 2 < T) {
            const int ns = (t + 2) % 3;
            if (t >= 1) { MBAR_WAIT(MBarr[ns], ph[ns]); ph[ns] ^= 1; }   // MMA(t-1) done
            load_tile(t + 2, ns); CP_COMMIT();
        }
    }
    {
        int e0 = (T >= 3) ? T - 3 : 0;
        for (int e = e0; e < T; ++e) { int j = e % 3; MBAR_WAIT(MBarr[j], ph[j]); ph[j] ^= 1; }
    }
    TC_FENCE_AFTER();
    if (wid < 4) {
        const int row = row0 + wid * 32 + lid;
        float* cp = C + (size_t)row * ldC + col0;
        float* zp = (EPI == 1)
            ? (g_Z + ((size_t)(z >> 4) * SEQ + row) * SEQ + col0) : (float*)0;
        for (int c0 = 0; c0 < 128; c0 += 32) {
            uint32_t r[32];
            TC_LD_X32(r, tmem + c0);
            TC_WAIT_LD();
            #pragma unroll
            for (int j = 0; j < 32; j += 4) {
                float4 o;
                if (EPI == 1) {
                    o.x = __expf(__uint_as_float(r[j + 0]) * scale);
                    o.y = __expf(__uint_as_float(r[j + 1]) * scale);
                    o.z = __expf(__uint_as_float(r[j + 2]) * scale);
                    o.w = __expf(__uint_as_float(r[j + 3]) * scale);
                    atomicAdd(zp + c0 + j + 0, o.x);
                    atomicAdd(zp + c0 + j + 1, o.y);
                    atomicAdd(zp + c0 + j + 2, o.z);
                    atomicAdd(zp + c0 + j + 3, o.w);
                } else {
                    o.x = __uint_as_float(r[j + 0]) * scale;
                    o.y = __uint_as_float(r[j + 1]) * scale;
                    o.z = __uint_as_float(r[j + 2]) * scale;
                    o.w = __uint_as_float(r[j + 3]) * scale;
                }
                *(float4*)&cp[c0 + j] = o;
            }
        }
    }
    __syncthreads();
    if (wid == 0) TC_DEALLOC(tmem, 128);
#else
    // FFMA fallback (compute_103 PTX pass only)
    char* sp = dsm + (sbase - raw);
    float* As = (float*)sp;
    float* Bs = As + 16 * 132;
    const int ty = tid >> 4, tx = tid & 15;
    float acc[8][8];
    #pragma unroll
    for (int i = 0; i < 8; i++)
        #pragma unroll
        for (int j = 0; j < 8; j++) acc[i][j] = 0.0f;
    for (int k0 = 0; k0 < K; k0 += 16) {
        for (int idx = tid; idx < 2048; idx += 256) {
            int r = idx >> 4, c = idx & 15;
            size_t ao = (size_t)(row0 + r) * ldA + k0 + c;
            size_t bo = (size_t)(col0 + r) * ldB + k0 + c;
            As[c * 132 + r] = __bfloat162float(Ah[ao]) + __bfloat162float(Al[ao]);
            Bs[c * 132 + r] = __bfloat162float(Bh[bo]) + __bfloat162float(Bl[bo]);
        }
        __syncthreads();
        #pragma unroll
        for (int k = 0; k < 16; k++) {
            float a[8], bb[8];
            #pragma unroll
            for (int i = 0; i < 8; i++) a[i]  = As[k * 132 + ty * 8 + i];
            #pragma unroll
            for (int j = 0; j < 8; j++) bb[j] = Bs[k * 132 + tx * 8 + j];
            #pragma unroll
            for (int i = 0; i < 8; i++)
                #pragma unroll
                for (int j = 0; j < 8; j++)
                    acc[i][j] = fmaf(a[i], bb[j], acc[i][j]);
        }
        __syncthreads();
    }
    #pragma unroll
    for (int i = 0; i < 8; i++)
        #pragma unroll
        for (int j = 0; j < 8; j++) {
            int row = row0 + ty * 8 + i, col = col0 + tx * 8 + j;
            if (EPI == 1) {
                float e = __expf(acc[i][j] * scale);
                C[(size_t)row * ldC + col] = e;
                atomicAdd(&g_Z[((size_t)(z >> 4) * SEQ + row) * SEQ + col], e);
            } else {
                C[(size_t)row * ldC + col] = acc[i][j] * scale;
            }
        }
#endif
}

// ---------------- PV: p = E * rZ (on the fly) @ V^T, 3P/4V-stage pipeline ----------------
__global__ void __launch_bounds__(256, 1) pv_tc()
{
    extern __shared__ char dsm[];
    uint32_t raw = smem_u32(dsm);
    uint32_t sbase = (raw + 1023) & ~1023u;
    char* sp = dsm + (sbase - raw);
    const int tid = threadIdx.x, wid = tid >> 5, lid = tid & 31;
    const int z = blockIdx.y;                 // b*16+h
    const int b = z >> 4, h = z & 15;
    const int l0 = blockIdx.x * 128;
    const float* Ep = g_E + (size_t)z * SEQ * SEQ;
    const float* Rp = g_Z + (size_t)b * SEQ * SEQ;   // holds 1/Z
    const __nv_bfloat16* Vhp = g_vth + (size_t)z * 64 * SEQ;
    const __nv_bfloat16* Vlp = g_vtl + (size_t)z * 64 * SEQ;
#if TC_OK
    // layout: ctrl[1024] | P stages 3 x (Ph 16K + Pl 16K) | V stages 4 x (Vh 8K + Vl 8K)
    const uint32_t POFF = sbase + 1024;
    const uint32_t VOFF = sbase + 1024 + 98304;
    uint32_t mb[4] = {sbase + 8, sbase + 16, sbase + 24, sbase + 32};

    if (wid == 0) {
        if (elect_one()) {
            MBAR_INIT(mb[0], 1); MBAR_INIT(mb[1], 1); MBAR_INIT(mb[2], 1); MBAR_INIT(mb[3], 1);
        }
        TC_ALLOC(sbase, 64);
        TC_RELINQ();
    }
    __syncthreads();
    uint32_t tmem;
    asm volatile("ld.shared.b32 %0, [%1];" : "=r"(tmem) : "r"(sbase));

    const uint32_t IDESC = (1u << 4) | (1u << 7) | (1u << 10) | (8u << 17) | (8u << 24);
    const int lr = tid >> 1;               // P row 0..127
    const int half = tid & 1;              // column half (32 each)

    float4 eb[8], zb[8];                   // prefetch regs for E and rZ

    auto prefetch = [&](int t) {
        const float* ep = Ep + (size_t)(l0 + lr) * SEQ + t * 64 + half * 32;
        const float* rp = Rp + (size_t)(l0 + lr) * SEQ + t * 64 + half * 32;
        #pragma unroll
        for (int i = 0; i < 8; ++i) {
            eb[i] = *(const float4*)(ep + i * 4);
            zb[i] = *(const float4*)(rp + i * 4);
        }
    };
    auto transform = [&](int t) {          // regs -> swizzled P hi/lo smem
        char* pb = sp + 1024 + (t % 3) * 32768;
        #pragma unroll
        for (int i = 0; i < 8; ++i) {
            float4 p;
            p.x = eb[i].x * zb[i].x; p.y = eb[i].y * zb[i].y;
            p.z = eb[i].z * zb[i].z; p.w = eb[i].w * zb[i].w;
            uint2 hv, lv;
            split4(p, hv, lv);
            uint32_t off = SWZ(lr * 128 + half * 64 + i * 8);
            *(uint2*)(pb + off)         = hv;
            *(uint2*)(pb + 16384 + off) = lv;
        }
    };
    auto vload = [&](int t) {
        uint32_t sb = VOFF + (t & 3) * 16384;
        #pragma unroll
        for (int it = 0; it < 2; ++it) {
            int idx = tid + it * 256;      // 64 rows x 8 chunks
            int r = idx >> 3, c = idx & 7;
            size_t vo = (size_t)r * SEQ + t * 64 + c * 8;
            uint32_t off = SWZ(r * 128 + c * 16);
            CP_ASYNC16(sb + off,        Vhp + vo);
            CP_ASYNC16(sb + 8192 + off, Vlp + vo);
        }
    };

    uint32_t ph4[4] = {0, 0, 0, 0};
    vload(0); CP_COMMIT();
    prefetch(0);
    for (int t = 0; t < 32; ++t) {
        if (t >= 3) {                       // MMA(t-3) done -> frees P stage t%3 and V stage (t+1)&3
            int j = (t + 1) & 3;
            MBAR_WAIT(mb[j], ph4[j]); ph4[j] ^= 1;
        }
        if (t + 1 < 32) { vload(t + 1); CP_COMMIT(); }
        transform(t);
        if (t + 1 < 32) prefetch(t + 1);
        if (t + 1 < 32) { CP_WAIT(1); } else { CP_WAIT(0); }
        __syncthreads();
        if (wid == 0) {
            FENCE_ASYNC();
            if (elect_one()) {
                uint32_t sbP = POFF + (t % 3) * 32768;
                uint32_t sbV = VOFF + (t & 3) * 16384;
                uint64_t dph = make_desc(sbP), dpl = make_desc(sbP + 16384);
                uint64_t dvh = make_desc(sbV), dvl = make_desc(sbV + 8192);
                #pragma unroll
                for (int ks = 0; ks < 4; ++ks) {
                    mma_bf16(tmem, dph + ks * 2, dvh + ks * 2, IDESC, (uint32_t)((t | ks) != 0));
                    mma_bf16(tmem, dph + ks * 2, dvl + ks * 2, IDESC, 1u);
                    mma_bf16(tmem, dpl + ks * 2, dvh + ks * 2, IDESC, 1u);
                }
                TC_COMMIT(mb[t & 3]);
            }
        }
    }
    for (int e = 29; e < 32; ++e) { int j = e & 3; MBAR_WAIT(mb[j], ph4[j]); ph4[j] ^= 1; }
    TC_FENCE_AFTER();
    if (wid < 4) {
        const int row = l0 + wid * 32 + lid;
        __nv_bfloat16* oh = g_ath + (size_t)(b * SEQ + row) * DIM + h * 64;
        __nv_bfloat16* ol = g_atl + (size_t)(b * SEQ + row) * DIM + h * 64;
        for (int c0 = 0; c0 < 64; c0 += 32) {
            uint32_t r[32];
            TC_LD_X32(r, tmem + c0);
            TC_WAIT_LD();
            #pragma unroll
            for (int j = 0; j < 32; j += 4) {
                float4 v;
                v.x = __uint_as_float(r[j + 0]); v.y = __uint_as_float(r[j + 1]);
                v.z = __uint_as_float(r[j + 2]); v.w = __uint_as_float(r[j + 3]);
                uint2 hv, lv;
                split4(v, hv, lv);
                *(uint2*)(oh + c0 + j) = hv;
                *(uint2*)(ol + c0 + j) = lv;
            }
        }
    }
    __syncthreads();
    if (wid == 0) TC_DEALLOC(tmem, 64);
#else
    // FFMA fallback
    float* Ps = (float*)sp;                  // [16][132]
    float* Vs = Ps + 16 * 132;               // [16][72]
    const int ty = tid >> 3;
    const int tx = tid & 7;
    float acc[4][8];
    #pragma unroll
    for (int i = 0; i < 4; i++)
        #pragma unroll
        for (int j = 0; j < 8; j++) acc[i][j] = 0.0f;
    for (int m0 = 0; m0 < SEQ; m0 += 16) {
        for (int idx = tid; idx < 2048; idx += 256) {
            int m = idx >> 7, l = idx & 127;
            size_t po = (size_t)(l0 + l) * SEQ + m0 + m;
            Ps[m * 132 + l] = Ep[po] * Rp[po];
        }
        for (int idx = tid; idx < 1024; idx += 256) {
            int m = idx >> 6, k = idx & 63;
            size_t vo = (size_t)k * SEQ + m0 + m;
            Vs[m * 72 + k] = __bfloat162float(Vhp[vo]) + __bfloat162float(Vlp[vo]);
        }
        __syncthreads();
        #pragma unroll
        for (int m = 0; m < 16; m++) {
            float a[4], bb[8];
            #pragma unroll
            for (int i = 0; i < 4; i++) a[i]  = Ps[m * 132 + ty * 4 + i];
            #pragma unroll
            for (int j = 0; j < 8; j++) bb[j] = Vs[m * 72 + tx * 8 + j];
            #pragma unroll
            for (int i = 0; i < 4; i++)
                #pragma unroll
                for (int j = 0; j < 8; j++)
                    acc[i][j] = fmaf(a[i], bb[j], acc[i][j]);
        }
        __syncthreads();
    }
    #pragma unroll
    for (int i = 0; i < 4; i++) {
        int row = l0 + ty * 4 + i;
        __nv_bfloat16* oh = g_ath + (size_t)(b * SEQ + row) * DIM + h * 64 + tx * 8;
        __nv_bfloat16* ol = g_atl + (size_t)(b * SEQ + row) * DIM + h * 64 + tx * 8;
        float4 v0 = make_float4(acc[i][0], acc[i][1], acc[i][2], acc[i][3]);
        float4 v1 = make_float4(acc[i][4], acc[i][5], acc[i][6], acc[i][7]);
        uint2 hv, lv;
        split4(v0, hv, lv);
        *(uint2*)oh = hv; *(uint2*)ol = lv;
        split4(v1, hv, lv);
        *(uint2*)(oh + 4) = hv; *(uint2*)(ol + 4) = lv;
    }
#endif
}

// ---------------- launch ----------------
extern "C" void kernel_launch(void* const* d_in, const int* in_sizes, int n_in,
                              void* d_out, int out_size)
{
    const float* x    = (const float*)d_in[0];
    const float* wqkv = (const float*)d_in[1];
    const float* wo   = (const float*)d_in[2];
    float* out = (float*)d_out;

    float *qkvp, *Ep, *Zp;
    __nv_bfloat16 *xh, *xl, *wqh, *wql, *woh, *wol;
    __nv_bfloat16 *qhh, *qhl, *khh, *khl, *ath, *atl;
    cudaGetSymbolAddress((void**)&qkvp, g_qkv);
    cudaGetSymbolAddress((void**)&Ep,   g_E);
    cudaGetSymbolAddress((void**)&Zp,   g_Z);
    cudaGetSymbolAddress((void**)&xh,   g_xh);
    cudaGetSymbolAddress((void**)&xl,   g_xl);
    cudaGetSymbolAddress((void**)&wqh,  g_wqh);
    cudaGetSymbolAddress((void**)&wql,  g_wql);
    cudaGetSymbolAddress((void**)&woh,  g_woh);
    cudaGetSymbolAddress((void**)&wol,  g_wol);
    cudaGetSymbolAddress((void**)&qhh,  g_qhh);
    cudaGetSymbolAddress((void**)&qhl,  g_qhl);
    cudaGetSymbolAddress((void**)&khh,  g_khh);
    cudaGetSymbolAddress((void**)&khl,  g_khl);
    cudaGetSymbolAddress((void**)&ath,  g_ath);
    cudaGetSymbolAddress((void**)&atl,  g_atl);

    const int SMEM_G = 2048 + 3 * 65536;            // 198656
    const int SMEM_P = 2048 + 3 * 32768 + 4 * 16384; // 165888
    cudaFuncSetAttribute(gemm_tc<0>, cudaFuncAttributeMaxDynamicSharedMemorySize, SMEM_G);
    cudaFuncSetAttribute(gemm_tc<1>, cudaFuncAttributeMaxDynamicSharedMemorySize, SMEM_G);
    cudaFuncSetAttribute(pv_tc,      cudaFuncAttributeMaxDynamicSharedMemorySize, SMEM_P);

    split_kernel<<<(BATCH * SEQ * DIM / 4 + 255) / 256, 256>>>((const float4*)x, xh, xl,
                                                               BATCH * SEQ * DIM / 4);
    transpose_split_kernel<<<dim3(TDIM / 32, DIM / 32), dim3(32, 8)>>>(wqkv, wqh, wql, DIM, TDIM);
    transpose_split_kernel<<<dim3(DIM / 32, DIM / 32), dim3(32, 8)>>>(wo, woh, wol, DIM, DIM);
    cudaMemsetAsync(Zp, 0, (size_t)BATCH * SEQ * SEQ * sizeof(float));

    // QKV projection
    gemm_tc<0><<<dim3(TDIM / 128, (BATCH * SEQ) / 128, 1), 256, SMEM_G>>>(
        xh, xl, wqh, wql, qkvp, DIM, DIM, DIM, TDIM, 0, 0, 0, 1.0f);

    conv_qk_kernel<<<(1 << 21) / 256, 256>>>();
    conv_vt_kernel<<<dim3(SEQ / 64, BATCH * HEADS), 256>>>();

    // scores -> E = exp(s/8), Z accumulated via atomics (all batches/heads)
    gemm_tc<1><<<dim3(SEQ / 128, SEQ / 128, BATCH * HEADS), 256, SMEM_G>>>(
        qhh, qhl, khh, khl, Ep,
        64, 64, 64, SEQ,
        (long long)SEQ * 64, (long long)SEQ * 64, (long long)SEQ * SEQ, 0.125f);

    // Z -> 1/Z
    rcp_kernel<<<(BATCH * SEQ * SEQ / 4 + 255) / 256, 256>>>((float4*)Zp, BATCH * SEQ * SEQ / 4);

    // PV (p formed on the fly from E and 1/Z)
    pv_tc<<<dim3(SEQ / 128, BATCH * HEADS), 256, SMEM_P>>>();

    // output projection
    gemm_tc<0><<<dim3(DIM / 128, (BATCH * SEQ) / 128, 1), 256, SMEM_G>>>(
        ath, atl, woh, wol, out, DIM, DIM, DIM, DIM, 0, 0, 0, 1.0f);
}